// round 15
// baseline (speedup 1.0000x reference)
#include <cuda_runtime.h>
#include <cuda_fp16.h>
#include <cstdint>
#include <math.h>

// ============================================================================
// GatedGNN B=256, N=80, D=1024, T=3 — mma.sync, BK=32, 3-stage single-sync
// (wait -> sync -> issue prefetch -> compute; wait MUST precede sync: cp.async
// groups are per-thread), XOR swizzle, 2 CTAs/SM.
// Precision per gate (compile-time specialized, measured ledger — CLOSED):
//   z   : 2-term  Ah*Wh + Ah*Wl
//   r   : 1-term  Ah*Wh
//   h_c : 3-term  Ah*Wh + Ah*Wl + Al*Wh
// ============================================================================

#define MR 20480
#define Dd 1024

// ---------------- device scratch ----------------
__device__ __align__(16) __half g_ACh[(size_t)MR * 2048];
__device__ __align__(16) __half g_ACl[(size_t)MR * 2048];
__device__ __align__(16) __half g_Hsh[(size_t)MR * 1024];
__device__ __align__(16) __half g_RHh[(size_t)MR * 1024];
__device__ __align__(16) __half g_RHl[(size_t)MR * 1024];
__device__ __align__(16) float  g_Z [(size_t)MR * 1024];
__device__ __align__(16) float  g_H1[(size_t)MR * 1024];
__device__ __align__(16) float  g_H2[(size_t)MR * 1024];
// weight pool (elems): W1w@0, W2w@2M, W3w@4M, W1u@6M, W2u@7M, W3u@8M
#define OW1w 0
#define OW2w 2097152
#define OW3w 4194304
#define OW1u 6291456
#define OW2u 7340032
#define OW3u 8388608
__device__ __align__(16) __half g_Wh[9437184];
__device__ __align__(16) __half g_Wl[9437184];

// ---------------- helpers ----------------
__device__ __forceinline__ uint32_t smem_u32(const void* p) {
    uint32_t a;
    asm("{ .reg .u64 t; cvta.to.shared.u64 t, %1; cvt.u32.u64 %0, t; }" : "=r"(a) : "l"(p));
    return a;
}
__device__ __forceinline__ void cp16(uint32_t dst, const void* src) {
    asm volatile("cp.async.cg.shared.global [%0], [%1], 16;" :: "r"(dst), "l"(src) : "memory");
}
#define CP_COMMIT() asm volatile("cp.async.commit_group;" ::: "memory")
#define CP_WAIT1()  asm volatile("cp.async.wait_group 1;" ::: "memory")
#define CP_WAIT0()  asm volatile("cp.async.wait_group 0;" ::: "memory")

__device__ __forceinline__ void ldsm4(uint32_t& r0, uint32_t& r1, uint32_t& r2, uint32_t& r3,
                                      uint32_t addr) {
    asm volatile("ldmatrix.sync.aligned.m8n8.x4.shared.b16 {%0,%1,%2,%3}, [%4];"
                 : "=r"(r0), "=r"(r1), "=r"(r2), "=r"(r3) : "r"(addr));
}
__device__ __forceinline__ void mma16816(float* c, uint32_t a0, uint32_t a1, uint32_t a2,
                                         uint32_t a3, uint32_t b0, uint32_t b1) {
    asm volatile(
        "mma.sync.aligned.m16n8k16.row.col.f32.f16.f16.f32 "
        "{%0,%1,%2,%3}, {%4,%5,%6,%7}, {%8,%9}, {%0,%1,%2,%3};"
        : "+f"(c[0]), "+f"(c[1]), "+f"(c[2]), "+f"(c[3])
        : "r"(a0), "r"(a1), "r"(a2), "r"(a3), "r"(b0), "r"(b1));
}
__device__ __forceinline__ void hsplit(float v, __half& h, __half& l) {
    h = __float2half(v);
    l = __float2half(v - __half2float(h));
}

// ============================================================================
// One-shot weight split, 1 launch
// ============================================================================
__global__ __launch_bounds__(256) void convert_w(
    const float* __restrict__ W1w, const float* __restrict__ W2w,
    const float* __restrict__ W3w, const float* __restrict__ W1u,
    const float* __restrict__ W2u, const float* __restrict__ W3u,
    __half* __restrict__ Wh, __half* __restrict__ Wl)
{
    size_t i = (size_t)blockIdx.x * 256 + threadIdx.x;
    if (i >= 9437184) return;
    const float* src;
    size_t off;
    if      (i < (size_t)OW2w) { src = W1w; off = 0; }
    else if (i < (size_t)OW3w) { src = W2w; off = OW2w; }
    else if (i < (size_t)OW1u) { src = W3w; off = OW3w; }
    else if (i < (size_t)OW2u) { src = W1u; off = OW1u; }
    else if (i < (size_t)OW3u) { src = W2u; off = OW2u; }
    else                       { src = W3u; off = OW3u; }
    float v = src[i - off];
    __half h, l; hsplit(v, h, l);
    Wh[i] = h; Wl[i] = l;
}

// ============================================================================
// Propagation: a_c = [inM@h | outM@h] -> fp16 hi/lo; h -> fp16 hi.
// inM/outM staged TRANSPOSED so the inner loop reads them as float4
// (same FMA order as before -> bit-identical results).
// ============================================================================
__global__ __launch_bounds__(256) void prop_split(
    const float* __restrict__ H,
    const float* __restrict__ inM, const float* __restrict__ outM,
    __half* __restrict__ ACh, __half* __restrict__ ACl,
    __half* __restrict__ Hsh)
{
    extern __shared__ float sm[];
    float* sh    = sm;               // [80][512]
    float* sInT  = sm + 80 * 512;    // [80][80] transposed: sInT[m*80+n]
    float* sOutT = sInT + 6400;

    const int tid = threadIdx.x;
    const int b   = blockIdx.y;
    const int dc  = blockIdx.x * 512 + 2 * tid;

    #pragma unroll 4
    for (int m = 0; m < 80; m++) {
        size_t hidx = (size_t)(b * 80 + m) * Dd + dc;
        float2 v = *(const float2*)(H + hidx);
        *(float2*)&sh[m * 512 + 2 * tid] = v;
        __half2 hv;
        hv.x = __float2half(v.x); hv.y = __float2half(v.y);
        *(__half2*)(Hsh + hidx) = hv;
    }
    for (int i = tid; i < 6400; i += 256) {
        const int n = i / 80, m = i % 80;       // i = n*80 + m
        sInT [m * 80 + n] = inM[i];
        sOutT[m * 80 + n] = outM[i];
    }
    __syncthreads();

    for (int n0 = 0; n0 < 80; n0 += 4) {
        float2 ai[4], ao[4];
        #pragma unroll
        for (int q = 0; q < 4; q++) { ai[q] = make_float2(0.f, 0.f); ao[q] = ai[q]; }
        #pragma unroll 4
        for (int m = 0; m < 80; m++) {
            float2 hm = *(const float2*)&sh[m * 512 + 2 * tid];
            float4 wi4 = *(const float4*)&sInT [m * 80 + n0];
            float4 wo4 = *(const float4*)&sOutT[m * 80 + n0];
            const float wi[4] = { wi4.x, wi4.y, wi4.z, wi4.w };
            const float wo[4] = { wo4.x, wo4.y, wo4.z, wo4.w };
            #pragma unroll
            for (int q = 0; q < 4; q++) {
                ai[q].x += wi[q] * hm.x; ai[q].y += wi[q] * hm.y;
                ao[q].x += wo[q] * hm.x; ao[q].y += wo[q] * hm.y;
            }
        }
        #pragma unroll
        for (int q = 0; q < 4; q++) {
            size_t base = (size_t)(b * 80 + n0 + q) * 2048 + dc;
            __half hx, lx, hy, ly;
            hsplit(ai[q].x, hx, lx); hsplit(ai[q].y, hy, ly);
            __half2 hv, lv; hv.x = hx; hv.y = hy; lv.x = lx; lv.y = ly;
            *(__half2*)(ACh + base) = hv;
            *(__half2*)(ACl + base) = lv;
            hsplit(ao[q].x, hx, lx); hsplit(ao[q].y, hy, ly);
            hv.x = hx; hv.y = hy; lv.x = lx; lv.y = ly;
            *(__half2*)(ACh + base + 1024) = hv;
            *(__half2*)(ACl + base + 1024) = lv;
        }
    }
}

// ============================================================================
// GEMM body, compile-time TERMS (3, 2 or 1).  C tile 128x128, K=3072, 8 warps
// (2Mx4N), warp tile 64x32, BK=32, 3-stage cp.async.
// Slab order (PROVEN, do not reorder): wait own group s -> sync (now ALL
// threads' group-s copies are complete) -> issue prefetch(s+2) -> compute.
// ============================================================================
#define ROWB 64u
#define MATB (128u * ROWB)       // 8192
#define STAGEB (4u * MATB)       // 32768: Ah, Al, Wh, Wl
#define NSLAB 96                 // 3072 / 32
#define GEMM_SMEM (3u * STAGEB)  // 98304

__device__ __forceinline__ uint32_t swz(uint32_t r, uint32_t c) {
    return r * ROWB + ((c ^ ((r >> 1) & 3u)) << 4);
}

template <int TERMS>
__device__ __forceinline__ void gemm_body(
    uint32_t smBase, int tid, int wid, int lane, int mBase, int jLocal,
    bool hi, int mode,
    const __half* __restrict__ ACh, const __half* __restrict__ ACl,
    const __half* __restrict__ A2h, const __half* __restrict__ A2l,
    const __half* __restrict__ WwH, const __half* __restrict__ WwL,
    const __half* __restrict__ WuH, const __half* __restrict__ WuL,
    const float* __restrict__ bw, const float* __restrict__ bu,
    const float* __restrict__ Hin, float* __restrict__ Zbuf,
    __half* __restrict__ RHh, __half* __restrict__ RHl,
    float* __restrict__ Hout)
{
    // 2048 16B-chunks per stage, 8 per thread.
    //   mat 1 (Al) loaded only when TERMS==3; mat 3 (Wl) only when TERMS>=2.
    auto load_stage = [&](int s) {
        const int kElem = s * 32;
        const bool uSeg = kElem >= 2048;
        const int k0 = uSeg ? kElem - 2048 : kElem;
        const int ld = uSeg ? 1024 : 2048;
        const __half* srcs[4] = { uSeg ? A2h : ACh, uSeg ? A2l : ACl,
                                  uSeg ? WuH : WwH, uSeg ? WuL : WwL };
        const uint32_t stage = smBase + (uint32_t)(s % 3) * STAGEB;
        #pragma unroll
        for (int i = 0; i < 8; i++) {
            const int id  = tid + i * 256;
            const int mat = id >> 9;
            if (TERMS < 3 && mat == 1) continue;    // compile-time skip Al
            if (TERMS < 2 && mat == 3) continue;    // compile-time skip Wl
            const uint32_t r = (id & 511) >> 2;
            const uint32_t c = id & 3;
            const int row = (mat < 2 ? mBase : jLocal) + (int)r;
            cp16(stage + (uint32_t)mat * MATB + swz(r, c),
                 srcs[mat] + (size_t)row * ld + k0 + c * 8);
        }
        CP_COMMIT();
    };

    float acc[4][4][4];
    #pragma unroll
    for (int mt = 0; mt < 4; mt++)
        #pragma unroll
        for (int nt = 0; nt < 4; nt++)
            #pragma unroll
            for (int q = 0; q < 4; q++) acc[mt][nt][q] = 0.f;

    load_stage(0);
    load_stage(1);

    const int warpM = (wid >> 2) * 64;
    const int warpN = (wid & 3) * 32;

    const uint32_t aRow = (uint32_t)(lane & 15);
    const uint32_t aCi  = (uint32_t)(lane >> 4);
    const uint32_t bRow = (uint32_t)((lane & 7) + ((lane & 16) >> 1));
    const uint32_t bCi  = (uint32_t)((lane >> 3) & 1);

    for (int s = 0; s < NSLAB; s++) {
        if (s + 1 < NSLAB) CP_WAIT1(); else CP_WAIT0();
        __syncthreads();
        if (s + 2 < NSLAB) load_stage(s + 2);

        const uint32_t stage = smBase + (uint32_t)(s % 3) * STAGEB;
        #pragma unroll
        for (int kk = 0; kk < 2; kk++) {
            uint32_t ah[4][4], al[4][4];
            #pragma unroll
            for (int mt = 0; mt < 4; mt++) {
                const uint32_t r = (uint32_t)(warpM + mt * 16) + aRow;
                const uint32_t rofs = swz(r, (uint32_t)kk * 2 + aCi);
                ldsm4(ah[mt][0], ah[mt][1], ah[mt][2], ah[mt][3], stage + rofs);
                if (TERMS == 3)
                    ldsm4(al[mt][0], al[mt][1], al[mt][2], al[mt][3],
                          stage + MATB + rofs);
            }
            uint32_t bh[4][2], bl[4][2];
            #pragma unroll
            for (int np = 0; np < 2; np++) {
                const uint32_t r = (uint32_t)(warpN + np * 16) + bRow;
                const uint32_t rofs = swz(r, (uint32_t)kk * 2 + bCi);
                uint32_t r0, r1, r2, r3;
                ldsm4(r0, r1, r2, r3, stage + 2u * MATB + rofs);
                bh[np * 2][0] = r0; bh[np * 2][1] = r1;
                bh[np * 2 + 1][0] = r2; bh[np * 2 + 1][1] = r3;
                if (TERMS >= 2) {
                    ldsm4(r0, r1, r2, r3, stage + 3u * MATB + rofs);
                    bl[np * 2][0] = r0; bl[np * 2][1] = r1;
                    bl[np * 2 + 1][0] = r2; bl[np * 2 + 1][1] = r3;
                }
            }
            #pragma unroll
            for (int mt = 0; mt < 4; mt++)
                #pragma unroll
                for (int nt = 0; nt < 4; nt++) {
                    mma16816(acc[mt][nt], ah[mt][0], ah[mt][1], ah[mt][2], ah[mt][3],
                             bh[nt][0], bh[nt][1]);
                    if (TERMS >= 2)
                        mma16816(acc[mt][nt], ah[mt][0], ah[mt][1], ah[mt][2], ah[mt][3],
                                 bl[nt][0], bl[nt][1]);
                    if (TERMS == 3)
                        mma16816(acc[mt][nt], al[mt][0], al[mt][1], al[mt][2], al[mt][3],
                                 bh[nt][0], bh[nt][1]);
                }
        }
    }

    // -------- epilogue --------
    const int g  = lane >> 2;
    const int tg = lane & 3;
    #pragma unroll
    for (int mt = 0; mt < 4; mt++) {
        #pragma unroll
        for (int nt = 0; nt < 4; nt++) {
            const int col = jLocal + warpN + nt * 8 + tg * 2;
            const float bws0 = __ldg(bw + col) + __ldg(bu + col);
            const float bws1 = __ldg(bw + col + 1) + __ldg(bu + col + 1);
            #pragma unroll
            for (int half = 0; half < 2; half++) {
                const int row = mBase + warpM + mt * 16 + g + half * 8;
                const size_t idx = (size_t)row * 1024 + col;
                float v0 = acc[mt][nt][half * 2 + 0] + bws0;
                float v1 = acc[mt][nt][half * 2 + 1] + bws1;
                if (mode == 0) {
                    float s0 = 1.0f / (1.0f + __expf(-v0));
                    float s1 = 1.0f / (1.0f + __expf(-v1));
                    if (!hi) {
                        Zbuf[idx] = s0; Zbuf[idx + 1] = s1;
                    } else {
                        float rh0 = s0 * __ldg(Hin + idx);
                        float rh1 = s1 * __ldg(Hin + idx + 1);
                        __half h0, l0, h1, l1;
                        hsplit(rh0, h0, l0); hsplit(rh1, h1, l1);
                        __half2 hv, lv; hv.x = h0; hv.y = h1; lv.x = l0; lv.y = l1;
                        *(__half2*)(RHh + idx) = hv;
                        *(__half2*)(RHl + idx) = lv;
                    }
                } else {
                    float g0 = tanhf(v0), g1 = tanhf(v1);
                    float z0 = __ldg(Zbuf + idx), z1 = __ldg(Zbuf + idx + 1);
                    float h0 = __ldg(Hin + idx),  h1 = __ldg(Hin + idx + 1);
                    Hout[idx]     = (1.0f - z0) * h0 + z0 * g0;
                    Hout[idx + 1] = (1.0f - z1) * h1 + z1 * g1;
                }
            }
        }
    }
}

__global__ __launch_bounds__(256, 2) void gemm_mma(
    const __half* __restrict__ ACh, const __half* __restrict__ ACl,
    const __half* __restrict__ A2h, const __half* __restrict__ A2l,
    const __half* __restrict__ Ww0h, const __half* __restrict__ Ww0l,
    const __half* __restrict__ Wu0h, const __half* __restrict__ Wu0l,
    const __half* __restrict__ Ww1h, const __half* __restrict__ Ww1l,
    const __half* __restrict__ Wu1h, const __half* __restrict__ Wu1l,
    const float* __restrict__ bw0, const float* __restrict__ bu0,
    const float* __restrict__ bw1, const float* __restrict__ bu1,
    const float* __restrict__ Hin, float* __restrict__ Zbuf,
    __half* __restrict__ RHh, __half* __restrict__ RHl,
    float* __restrict__ Hout, int mode)
{
    extern __shared__ char dynsm[];
    const uint32_t smBase = smem_u32(dynsm);

    const int tid  = threadIdx.x;
    const int wid  = tid >> 5;
    const int lane = tid & 31;
    const int mBase = blockIdx.y * 128;
    const int jBase = blockIdx.x * 128;
    const bool hi = (mode == 0) && (jBase >= 1024);
    const int jLocal = jBase & 1023;

    const __half* WwH = hi ? Ww1h : Ww0h;
    const __half* WwL = hi ? Ww1l : Ww0l;
    const __half* WuH = hi ? Wu1h : Wu0h;
    const __half* WuL = hi ? Wu1l : Wu0l;
    const float* bw = hi ? bw1 : bw0;
    const float* bu = hi ? bu1 : bu0;

    if (hi) {
        // r gate: 1-term
        gemm_body<1>(smBase, tid, wid, lane, mBase, jLocal, hi, mode,
                     ACh, ACl, A2h, A2l, WwH, WwL, WuH, WuL, bw, bu,
                     Hin, Zbuf, RHh, RHl, Hout);
    } else if (mode == 0) {
        // z gate: 2-term
        gemm_body<2>(smBase, tid, wid, lane, mBase, jLocal, hi, mode,
                     ACh, ACl, A2h, A2l, WwH, WwL, WuH, WuL, bw, bu,
                     Hin, Zbuf, RHh, RHl, Hout);
    } else {
        // h_c: 3-term
        gemm_body<3>(smBase, tid, wid, lane, mBase, jLocal, hi, mode,
                     ACh, ACl, A2h, A2l, WwH, WwL, WuH, WuL, bw, bu,
                     Hin, Zbuf, RHh, RHl, Hout);
    }
}

// ============================================================================
extern "C" void kernel_launch(void* const* d_in, const int* in_sizes, int n_in,
                              void* d_out, int out_size)
{
    const float* x    = (const float*)d_in[0];
    const float* inM  = (const float*)d_in[1];
    const float* outM = (const float*)d_in[2];
    const float* W1w  = (const float*)d_in[3];
    const float* b1w  = (const float*)d_in[4];
    const float* W1u  = (const float*)d_in[5];
    const float* b1u  = (const float*)d_in[6];
    const float* W2w  = (const float*)d_in[7];
    const float* b2w  = (const float*)d_in[8];
    const float* W2u  = (const float*)d_in[9];
    const float* b2u  = (const float*)d_in[10];
    const float* W3w  = (const float*)d_in[11];
    const float* b3w  = (const float*)d_in[12];
    const float* W3u  = (const float*)d_in[13];
    const float* b3u  = (const float*)d_in[14];
    // d_in[15] = timeStep (always 3)

    __half *ACh, *ACl, *Hsh, *RHh, *RHl, *Wh, *Wl;
    float *Z, *H1, *H2;
    cudaGetSymbolAddress((void**)&ACh, g_ACh);
    cudaGetSymbolAddress((void**)&ACl, g_ACl);
    cudaGetSymbolAddress((void**)&Hsh, g_Hsh);
    cudaGetSymbolAddress((void**)&RHh, g_RHh);
    cudaGetSymbolAddress((void**)&RHl, g_RHl);
    cudaGetSymbolAddress((void**)&Z,  g_Z);
    cudaGetSymbolAddress((void**)&H1, g_H1);
    cudaGetSymbolAddress((void**)&H2, g_H2);
    cudaGetSymbolAddress((void**)&Wh, g_Wh);
    cudaGetSymbolAddress((void**)&Wl, g_Wl);

    convert_w<<<(9437184 + 255) / 256, 256>>>(W1w, W2w, W3w, W1u, W2u, W3u, Wh, Wl);

    const int propSmem = (80 * 512 + 2 * 6400) * sizeof(float);   // 215040
    cudaFuncSetAttribute(prop_split, cudaFuncAttributeMaxDynamicSharedMemorySize, propSmem);
    cudaFuncSetAttribute(gemm_mma, cudaFuncAttributeMaxDynamicSharedMemorySize, GEMM_SMEM);

    const float* Hin = x;
    float* Houts[3] = { H1, H2, (float*)d_out };

    for (int t = 0; t < 3; t++) {
        prop_split<<<dim3(2, 256), 256, propSmem>>>(Hin, inM, outM, ACh, ACl, Hsh);

        // mode 0: z (2-term) + r (1-term) -> Z, RH hi/lo
        gemm_mma<<<dim3(16, 160), 256, GEMM_SMEM>>>(
            ACh, ACl, Hsh, nullptr,
            Wh + OW1w, Wl + OW1w, Wh + OW1u, Wl + OW1u,
            Wh + OW2w, Wl + OW2w, Wh + OW2u, Wl + OW2u,
            b1w, b1u, b2w, b2u,
            Hin, Z, RHh, RHl, nullptr, 0);

        // mode 1: h_c (3-term) + gated update -> Hout
        gemm_mma<<<dim3(8, 160), 256, GEMM_SMEM>>>(
            ACh, ACl, RHh, RHl,
            Wh + OW3w, Wl + OW3w, Wh + OW3u, Wl + OW3u,
            Wh + OW3w, Wl + OW3w, Wh + OW3u, Wl + OW3u,
            b3w, b3u, b3w, b3u,
            Hin, Z, nullptr, nullptr, Houts[t], 1);

        Hin = Houts[t];
    }
}

// round 16
// speedup vs baseline: 1.0118x; 1.0118x over previous
#include <cuda_runtime.h>
#include <cuda_fp16.h>
#include <cstdint>
#include <math.h>

// ============================================================================
// GatedGNN B=256, N=80, D=1024, T=3 — mma.sync, BK=32, 3-stage single-sync
// pipeline, XOR swizzle, 2 CTAs/SM.  z/r/h_c FUSED into one launch per step:
// h_c tiles acquire per-rowblock flags (released by the 16 z+r tiles of that
// rowblock) right before their first RH-dependent prefetch (s==62).
// Precision per gate (measured ledger — CLOSED):
//   z   : 2-term  Ah*Wh + Ah*Wl
//   r   : 1-term  Ah*Wh
//   h_c : 3-term  Ah*Wh + Ah*Wl + Al*Wh
// ============================================================================

#define MR 20480
#define Dd 1024

// ---------------- device scratch ----------------
__device__ __align__(16) __half g_ACh[(size_t)MR * 2048];
__device__ __align__(16) __half g_ACl[(size_t)MR * 2048];
__device__ __align__(16) __half g_Hsh[(size_t)MR * 1024];
__device__ __align__(16) __half g_RHh[(size_t)MR * 1024];
__device__ __align__(16) __half g_RHl[(size_t)MR * 1024];
__device__ __align__(16) float  g_Z [(size_t)MR * 1024];
__device__ __align__(16) float  g_H1[(size_t)MR * 1024];
__device__ __align__(16) float  g_H2[(size_t)MR * 1024];
__device__ int g_flags[512];                 // 160 rowblocks x 3 steps
// weight pool (elems): W1w@0, W2w@2M, W3w@4M, W1u@6M, W2u@7M, W3u@8M
#define OW1w 0
#define OW2w 2097152
#define OW3w 4194304
#define OW1u 6291456
#define OW2u 7340032
#define OW3u 8388608
__device__ __align__(16) __half g_Wh[9437184];
__device__ __align__(16) __half g_Wl[9437184];

// ---------------- helpers ----------------
__device__ __forceinline__ uint32_t smem_u32(const void* p) {
    uint32_t a;
    asm("{ .reg .u64 t; cvta.to.shared.u64 t, %1; cvt.u32.u64 %0, t; }" : "=r"(a) : "l"(p));
    return a;
}
__device__ __forceinline__ void cp16(uint32_t dst, const void* src) {
    asm volatile("cp.async.cg.shared.global [%0], [%1], 16;" :: "r"(dst), "l"(src) : "memory");
}
#define CP_COMMIT() asm volatile("cp.async.commit_group;" ::: "memory")
#define CP_WAIT1()  asm volatile("cp.async.wait_group 1;" ::: "memory")
#define CP_WAIT0()  asm volatile("cp.async.wait_group 0;" ::: "memory")

__device__ __forceinline__ void ldsm4(uint32_t& r0, uint32_t& r1, uint32_t& r2, uint32_t& r3,
                                      uint32_t addr) {
    asm volatile("ldmatrix.sync.aligned.m8n8.x4.shared.b16 {%0,%1,%2,%3}, [%4];"
                 : "=r"(r0), "=r"(r1), "=r"(r2), "=r"(r3) : "r"(addr));
}
__device__ __forceinline__ void mma16816(float* c, uint32_t a0, uint32_t a1, uint32_t a2,
                                         uint32_t a3, uint32_t b0, uint32_t b1) {
    asm volatile(
        "mma.sync.aligned.m16n8k16.row.col.f32.f16.f16.f32 "
        "{%0,%1,%2,%3}, {%4,%5,%6,%7}, {%8,%9}, {%0,%1,%2,%3};"
        : "+f"(c[0]), "+f"(c[1]), "+f"(c[2]), "+f"(c[3])
        : "r"(a0), "r"(a1), "r"(a2), "r"(a3), "r"(b0), "r"(b1));
}
__device__ __forceinline__ void hsplit(float v, __half& h, __half& l) {
    h = __float2half(v);
    l = __float2half(v - __half2float(h));
}
__device__ __forceinline__ int ld_acquire(const int* p) {
    int v;
    asm volatile("ld.acquire.gpu.global.b32 %0, [%1];" : "=r"(v) : "l"(p) : "memory");
    return v;
}

// ============================================================================
// One-shot weight split, 1 launch
// ============================================================================
__global__ __launch_bounds__(256) void convert_w(
    const float* __restrict__ W1w, const float* __restrict__ W2w,
    const float* __restrict__ W3w, const float* __restrict__ W1u,
    const float* __restrict__ W2u, const float* __restrict__ W3u,
    __half* __restrict__ Wh, __half* __restrict__ Wl)
{
    size_t i = (size_t)blockIdx.x * 256 + threadIdx.x;
    if (i >= 9437184) return;
    const float* src;
    size_t off;
    if      (i < (size_t)OW2w) { src = W1w; off = 0; }
    else if (i < (size_t)OW3w) { src = W2w; off = OW2w; }
    else if (i < (size_t)OW1u) { src = W3w; off = OW3w; }
    else if (i < (size_t)OW2u) { src = W1u; off = OW1u; }
    else if (i < (size_t)OW3u) { src = W2u; off = OW2u; }
    else                       { src = W3u; off = OW3u; }
    float v = src[i - off];
    __half h, l; hsplit(v, h, l);
    Wh[i] = h; Wl[i] = l;
}

// ============================================================================
// Propagation: a_c = [inM@h | outM@h] -> fp16 hi/lo; h -> fp16 hi.
// ============================================================================
__global__ __launch_bounds__(256) void prop_split(
    const float* __restrict__ H,
    const float* __restrict__ inM, const float* __restrict__ outM,
    __half* __restrict__ ACh, __half* __restrict__ ACl,
    __half* __restrict__ Hsh)
{
    extern __shared__ float sm[];
    float* sh    = sm;               // [80][512]
    float* sInT  = sm + 80 * 512;    // [80][80] transposed
    float* sOutT = sInT + 6400;

    const int tid = threadIdx.x;
    const int b   = blockIdx.y;
    const int dc  = blockIdx.x * 512 + 2 * tid;

    #pragma unroll 4
    for (int m = 0; m < 80; m++) {
        size_t hidx = (size_t)(b * 80 + m) * Dd + dc;
        float2 v = *(const float2*)(H + hidx);
        *(float2*)&sh[m * 512 + 2 * tid] = v;
        __half2 hv;
        hv.x = __float2half(v.x); hv.y = __float2half(v.y);
        *(__half2*)(Hsh + hidx) = hv;
    }
    for (int i = tid; i < 6400; i += 256) {
        const int n = i / 80, m = i % 80;
        sInT [m * 80 + n] = inM[i];
        sOutT[m * 80 + n] = outM[i];
    }
    __syncthreads();

    for (int n0 = 0; n0 < 80; n0 += 4) {
        float2 ai[4], ao[4];
        #pragma unroll
        for (int q = 0; q < 4; q++) { ai[q] = make_float2(0.f, 0.f); ao[q] = ai[q]; }
        #pragma unroll 4
        for (int m = 0; m < 80; m++) {
            float2 hm = *(const float2*)&sh[m * 512 + 2 * tid];
            float4 wi4 = *(const float4*)&sInT [m * 80 + n0];
            float4 wo4 = *(const float4*)&sOutT[m * 80 + n0];
            const float wi[4] = { wi4.x, wi4.y, wi4.z, wi4.w };
            const float wo[4] = { wo4.x, wo4.y, wo4.z, wo4.w };
            #pragma unroll
            for (int q = 0; q < 4; q++) {
                ai[q].x += wi[q] * hm.x; ai[q].y += wi[q] * hm.y;
                ao[q].x += wo[q] * hm.x; ao[q].y += wo[q] * hm.y;
            }
        }
        #pragma unroll
        for (int q = 0; q < 4; q++) {
            size_t base = (size_t)(b * 80 + n0 + q) * 2048 + dc;
            __half hx, lx, hy, ly;
            hsplit(ai[q].x, hx, lx); hsplit(ai[q].y, hy, ly);
            __half2 hv, lv; hv.x = hx; hv.y = hy; lv.x = lx; lv.y = ly;
            *(__half2*)(ACh + base) = hv;
            *(__half2*)(ACl + base) = lv;
            hsplit(ao[q].x, hx, lx); hsplit(ao[q].y, hy, ly);
            hv.x = hx; hv.y = hy; lv.x = lx; lv.y = ly;
            *(__half2*)(ACh + base + 1024) = hv;
            *(__half2*)(ACl + base + 1024) = lv;
        }
    }
}

// ============================================================================
// GEMM body, compile-time TERMS (3/2/1) and WAIT (h_c acquires rowblock flag
// at s==62, right before prefetching the first RH-dependent slab s+2==64).
// C tile 128x128, K=3072, 8 warps (2Mx4N), BK=32, 3-stage cp.async.
// Slab order (PROVEN): wait own group -> sync -> issue prefetch -> compute.
// ============================================================================
#define ROWB 64u
#define MATB (128u * ROWB)       // 8192
#define STAGEB (4u * MATB)       // 32768: Ah, Al, Wh, Wl
#define NSLAB 96                 // 3072 / 32
#define GEMM_SMEM (3u * STAGEB)  // 98304

__device__ __forceinline__ uint32_t swz(uint32_t r, uint32_t c) {
    return r * ROWB + ((c ^ ((r >> 1) & 3u)) << 4);
}

template <int TERMS, bool WAIT>
__device__ __forceinline__ void gemm_body(
    uint32_t smBase, int tid, int wid, int lane, int mBase, int jLocal,
    bool hi, int mode, const int* flagRow,
    const __half* __restrict__ ACh, const __half* __restrict__ ACl,
    const __half* __restrict__ A2h, const __half* __restrict__ A2l,
    const __half* __restrict__ WwH, const __half* __restrict__ WwL,
    const __half* __restrict__ WuH, const __half* __restrict__ WuL,
    const float* __restrict__ bw, const float* __restrict__ bu,
    const float* __restrict__ Hin, float* __restrict__ Zbuf,
    __half* __restrict__ RHh, __half* __restrict__ RHl,
    float* __restrict__ Hout)
{
    auto load_stage = [&](int s) {
        const int kElem = s * 32;
        const bool uSeg = kElem >= 2048;
        const int k0 = uSeg ? kElem - 2048 : kElem;
        const int ld = uSeg ? 1024 : 2048;
        const __half* srcs[4] = { uSeg ? A2h : ACh, uSeg ? A2l : ACl,
                                  uSeg ? WuH : WwH, uSeg ? WuL : WwL };
        const uint32_t stage = smBase + (uint32_t)(s % 3) * STAGEB;
        #pragma unroll
        for (int i = 0; i < 8; i++) {
            const int id  = tid + i * 256;
            const int mat = id >> 9;
            if (TERMS < 3 && mat == 1) continue;    // compile-time skip Al
            if (TERMS < 2 && mat == 3) continue;    // compile-time skip Wl
            const uint32_t r = (id & 511) >> 2;
            const uint32_t c = id & 3;
            const int row = (mat < 2 ? mBase : jLocal) + (int)r;
            cp16(stage + (uint32_t)mat * MATB + swz(r, c),
                 srcs[mat] + (size_t)row * ld + k0 + c * 8);
        }
        CP_COMMIT();
    };

    float acc[4][4][4];
    #pragma unroll
    for (int mt = 0; mt < 4; mt++)
        #pragma unroll
        for (int nt = 0; nt < 4; nt++)
            #pragma unroll
            for (int q = 0; q < 4; q++) acc[mt][nt][q] = 0.f;

    load_stage(0);
    load_stage(1);

    const int warpM = (wid >> 2) * 64;
    const int warpN = (wid & 3) * 32;

    const uint32_t aRow = (uint32_t)(lane & 15);
    const uint32_t aCi  = (uint32_t)(lane >> 4);
    const uint32_t bRow = (uint32_t)((lane & 7) + ((lane & 16) >> 1));
    const uint32_t bCi  = (uint32_t)((lane >> 3) & 1);

    for (int s = 0; s < NSLAB; s++) {
        if (s + 1 < NSLAB) CP_WAIT1(); else CP_WAIT0();
        __syncthreads();
        if (WAIT && s == 62) {
            // acquire: all 16 z+r tiles of this rowblock done (RH + Z ready)
            if (tid == 0) {
                while (ld_acquire(flagRow) < 16) __nanosleep(64);
            }
            __syncthreads();
        }
        if (s + 2 < NSLAB) load_stage(s + 2);

        const uint32_t stage = smBase + (uint32_t)(s % 3) * STAGEB;
        #pragma unroll
        for (int kk = 0; kk < 2; kk++) {
            uint32_t ah[4][4], al[4][4];
            #pragma unroll
            for (int mt = 0; mt < 4; mt++) {
                const uint32_t r = (uint32_t)(warpM + mt * 16) + aRow;
                const uint32_t rofs = swz(r, (uint32_t)kk * 2 + aCi);
                ldsm4(ah[mt][0], ah[mt][1], ah[mt][2], ah[mt][3], stage + rofs);
                if (TERMS == 3)
                    ldsm4(al[mt][0], al[mt][1], al[mt][2], al[mt][3],
                          stage + MATB + rofs);
            }
            uint32_t bh[4][2], bl[4][2];
            #pragma unroll
            for (int np = 0; np < 2; np++) {
                const uint32_t r = (uint32_t)(warpN + np * 16) + bRow;
                const uint32_t rofs = swz(r, (uint32_t)kk * 2 + bCi);
                uint32_t r0, r1, r2, r3;
                ldsm4(r0, r1, r2, r3, stage + 2u * MATB + rofs);
                bh[np * 2][0] = r0; bh[np * 2][1] = r1;
                bh[np * 2 + 1][0] = r2; bh[np * 2 + 1][1] = r3;
                if (TERMS >= 2) {
                    ldsm4(r0, r1, r2, r3, stage + 3u * MATB + rofs);
                    bl[np * 2][0] = r0; bl[np * 2][1] = r1;
                    bl[np * 2 + 1][0] = r2; bl[np * 2 + 1][1] = r3;
                }
            }
            #pragma unroll
            for (int mt = 0; mt < 4; mt++)
                #pragma unroll
                for (int nt = 0; nt < 4; nt++) {
                    mma16816(acc[mt][nt], ah[mt][0], ah[mt][1], ah[mt][2], ah[mt][3],
                             bh[nt][0], bh[nt][1]);
                    if (TERMS >= 2)
                        mma16816(acc[mt][nt], ah[mt][0], ah[mt][1], ah[mt][2], ah[mt][3],
                                 bl[nt][0], bl[nt][1]);
                    if (TERMS == 3)
                        mma16816(acc[mt][nt], al[mt][0], al[mt][1], al[mt][2], al[mt][3],
                                 bh[nt][0], bh[nt][1]);
                }
        }
    }

    // -------- epilogue --------
    const int g  = lane >> 2;
    const int tg = lane & 3;
    #pragma unroll
    for (int mt = 0; mt < 4; mt++) {
        #pragma unroll
        for (int nt = 0; nt < 4; nt++) {
            const int col = jLocal + warpN + nt * 8 + tg * 2;
            const float bws0 = __ldg(bw + col) + __ldg(bu + col);
            const float bws1 = __ldg(bw + col + 1) + __ldg(bu + col + 1);
            #pragma unroll
            for (int half = 0; half < 2; half++) {
                const int row = mBase + warpM + mt * 16 + g + half * 8;
                const size_t idx = (size_t)row * 1024 + col;
                float v0 = acc[mt][nt][half * 2 + 0] + bws0;
                float v1 = acc[mt][nt][half * 2 + 1] + bws1;
                if (mode == 0) {
                    float s0 = 1.0f / (1.0f + __expf(-v0));
                    float s1 = 1.0f / (1.0f + __expf(-v1));
                    if (!hi) {
                        Zbuf[idx] = s0; Zbuf[idx + 1] = s1;
                    } else {
                        float rh0 = s0 * __ldg(Hin + idx);
                        float rh1 = s1 * __ldg(Hin + idx + 1);
                        __half h0, l0, h1, l1;
                        hsplit(rh0, h0, l0); hsplit(rh1, h1, l1);
                        __half2 hv, lv; hv.x = h0; hv.y = h1; lv.x = l0; lv.y = l1;
                        *(__half2*)(RHh + idx) = hv;
                        *(__half2*)(RHl + idx) = lv;
                    }
                } else {
                    float g0 = tanhf(v0), g1 = tanhf(v1);
                    float z0 = __ldg(Zbuf + idx), z1 = __ldg(Zbuf + idx + 1);
                    float h0 = __ldg(Hin + idx),  h1 = __ldg(Hin + idx + 1);
                    Hout[idx]     = (1.0f - z0) * h0 + z0 * g0;
                    Hout[idx + 1] = (1.0f - z1) * h1 + z1 * g1;
                }
            }
        }
    }
}

// ============================================================================
// Fused per-step GEMM launch: 3840 CTAs.
//   bid < 2560 : mode0 tiles, grouped 16 per rowblock (8 z + 8 r);
//                release rowblock flag after epilogue.
//   bid >= 2560: h_c tiles (8 per rowblock); acquire flag at s==62.
// ============================================================================
__global__ __launch_bounds__(256, 2) void gemm_fused(
    const __half* __restrict__ ACh, const __half* __restrict__ ACl,
    const __half* __restrict__ Hsh,
    const __half* __restrict__ RHhIn, const __half* __restrict__ RHlIn,
    const __half* __restrict__ Wh, const __half* __restrict__ Wl,
    const float* __restrict__ b1w, const float* __restrict__ b1u,
    const float* __restrict__ b2w, const float* __restrict__ b2u,
    const float* __restrict__ b3w, const float* __restrict__ b3u,
    const float* __restrict__ Hin, float* __restrict__ Zbuf,
    __half* __restrict__ RHh, __half* __restrict__ RHl,
    float* __restrict__ Hout, int* __restrict__ flags)
{
    extern __shared__ char dynsm[];
    const uint32_t smBase = smem_u32(dynsm);

    const int tid  = threadIdx.x;
    const int wid  = tid >> 5;
    const int lane = tid & 31;
    const int bid  = blockIdx.x;

    if (bid < 2560) {
        const int rowblock = bid >> 4;
        const int within   = bid & 15;
        const bool hi      = within >= 8;
        const int mBase    = rowblock << 7;
        const int jLocal   = (within & 7) << 7;
        int* flagRow = flags + rowblock;

        if (hi) {
            // r gate: 1-term
            gemm_body<1, false>(smBase, tid, wid, lane, mBase, jLocal, true, 0,
                                nullptr,
                                ACh, ACl, Hsh, nullptr,
                                Wh + OW2w, Wl + OW2w, Wh + OW2u, Wl + OW2u,
                                b2w, b2u, Hin, Zbuf, RHh, RHl, nullptr);
        } else {
            // z gate: 2-term
            gemm_body<2, false>(smBase, tid, wid, lane, mBase, jLocal, false, 0,
                                nullptr,
                                ACh, ACl, Hsh, nullptr,
                                Wh + OW1w, Wl + OW1w, Wh + OW1u, Wl + OW1u,
                                b1w, b1u, Hin, Zbuf, RHh, RHl, nullptr);
        }
        // release: all this CTA's stores, then count the tile
        __threadfence();
        __syncthreads();
        if (tid == 0) atomicAdd(flagRow, 1);
    } else {
        const int t2       = bid - 2560;
        const int rowblock = t2 >> 3;
        const int mBase    = rowblock << 7;
        const int jLocal   = (t2 & 7) << 7;
        const int* flagRow = flags + rowblock;

        // h_c: 3-term, waits on rowblock flag before RH-dependent prefetch
        gemm_body<3, true>(smBase, tid, wid, lane, mBase, jLocal, false, 1,
                           flagRow,
                           ACh, ACl, RHhIn, RHlIn,
                           Wh + OW3w, Wl + OW3w, Wh + OW3u, Wl + OW3u,
                           b3w, b3u, Hin, Zbuf, nullptr, nullptr, Hout);
    }
}

// ============================================================================
extern "C" void kernel_launch(void* const* d_in, const int* in_sizes, int n_in,
                              void* d_out, int out_size)
{
    const float* x    = (const float*)d_in[0];
    const float* inM  = (const float*)d_in[1];
    const float* outM = (const float*)d_in[2];
    const float* W1w  = (const float*)d_in[3];
    const float* b1w  = (const float*)d_in[4];
    const float* W1u  = (const float*)d_in[5];
    const float* b1u  = (const float*)d_in[6];
    const float* W2w  = (const float*)d_in[7];
    const float* b2w  = (const float*)d_in[8];
    const float* W2u  = (const float*)d_in[9];
    const float* b2u  = (const float*)d_in[10];
    const float* W3w  = (const float*)d_in[11];
    const float* b3w  = (const float*)d_in[12];
    const float* W3u  = (const float*)d_in[13];
    const float* b3u  = (const float*)d_in[14];
    // d_in[15] = timeStep (always 3)

    __half *ACh, *ACl, *Hsh, *RHh, *RHl, *Wh, *Wl;
    float *Z, *H1, *H2;
    int* flags;
    cudaGetSymbolAddress((void**)&ACh, g_ACh);
    cudaGetSymbolAddress((void**)&ACl, g_ACl);
    cudaGetSymbolAddress((void**)&Hsh, g_Hsh);
    cudaGetSymbolAddress((void**)&RHh, g_RHh);
    cudaGetSymbolAddress((void**)&RHl, g_RHl);
    cudaGetSymbolAddress((void**)&Z,  g_Z);
    cudaGetSymbolAddress((void**)&H1, g_H1);
    cudaGetSymbolAddress((void**)&H2, g_H2);
    cudaGetSymbolAddress((void**)&Wh, g_Wh);
    cudaGetSymbolAddress((void**)&Wl, g_Wl);
    cudaGetSymbolAddress((void**)&flags, g_flags);

    cudaMemsetAsync(flags, 0, 512 * sizeof(int), 0);

    convert_w<<<(9437184 + 255) / 256, 256>>>(W1w, W2w, W3w, W1u, W2u, W3u, Wh, Wl);

    const int propSmem = (80 * 512 + 2 * 6400) * sizeof(float);   // 215040
    cudaFuncSetAttribute(prop_split, cudaFuncAttributeMaxDynamicSharedMemorySize, propSmem);
    cudaFuncSetAttribute(gemm_fused, cudaFuncAttributeMaxDynamicSharedMemorySize, GEMM_SMEM);

    const float* Hin = x;
    float* Houts[3] = { H1, H2, (float*)d_out };

    for (int t = 0; t < 3; t++) {
        prop_split<<<dim3(2, 256), 256, propSmem>>>(Hin, inM, outM, ACh, ACl, Hsh);

        gemm_fused<<<3840, 256, GEMM_SMEM>>>(
            ACh, ACl, Hsh, RHh, RHl, Wh, Wl,
            b1w, b1u, b2w, b2u, b3w, b3u,
            Hin, Z, RHh, RHl, Houts[t], flags + t * 160);

        Hin = Houts[t];
    }
}